// round 1
// baseline (speedup 1.0000x reference)
#include <cuda_runtime.h>

// FoldLayer (overlap-add) as a pure gather.
// Input:  patches (B=16, GH=64, GW=64, K*K*C = 9*128) float32, kernel-major
// Output: (B=16, 128, 128, C=128) float32
//
// Canvas coords: y = yo + PAD (PAD=1), contributors satisfy 2*gy + i == y.
// y odd  -> (gy=y>>1, i=1)
// y even -> (gy=y/2, i=0) if gy<64 ; (gy=y/2-1, i=2)
// Same along x. Each output element sums 1, 2 or 4 patch elements.
//
// Vectorized float4 over channels: 32 float4 per pixel, one warp per pixel
// -> no intra-warp divergence, fully coalesced 512B segments.

namespace {
constexpr int B   = 16;
constexpr int G   = 64;    // GH = GW
constexpr int C4  = 32;    // C/4
constexpr int OUT = 128;
// input float4 strides
constexpr int PATCH_F4 = 9 * C4;        // 288 float4 per (b,gy,gx)
}

__global__ __launch_bounds__(256) void fold_gather_kernel(
    const float4* __restrict__ in, float4* __restrict__ out)
{
    int idx = blockIdx.x * blockDim.x + threadIdx.x;
    // total = B*OUT*OUT*C4 = 8388608 threads, launched exactly
    int c4  = idx & (C4 - 1);
    int pix = idx >> 5;
    int xo  = pix & (OUT - 1);
    int t   = pix >> 7;
    int yo  = t & (OUT - 1);
    int b   = t >> 7;

    int y = yo + 1;
    int x = xo + 1;

    // Row contributors (gy, i)
    int gy[2], ki[2], nrow;
    if (y & 1) {
        gy[0] = y >> 1; ki[0] = 1; nrow = 1;
    } else {
        int g0 = y >> 1;
        nrow = 0;
        if (g0 < G) { gy[nrow] = g0;     ki[nrow] = 0; nrow++; }
                      gy[nrow] = g0 - 1; ki[nrow] = 2; nrow++;
    }

    // Col contributors (gx, j)
    int gx[2], kj[2], ncol;
    if (x & 1) {
        gx[0] = x >> 1; kj[0] = 1; ncol = 1;
    } else {
        int g0 = x >> 1;
        ncol = 0;
        if (g0 < G) { gx[ncol] = g0;     kj[ncol] = 0; ncol++; }
                      gx[ncol] = g0 - 1; kj[ncol] = 2; ncol++;
    }

    float4 acc = make_float4(0.f, 0.f, 0.f, 0.f);
    #pragma unroll 2
    for (int r = 0; r < nrow; r++) {
        int rowbase = (b * G + gy[r]) * G;
        #pragma unroll 2
        for (int cc = 0; cc < ncol; cc++) {
            int off = (rowbase + gx[cc]) * PATCH_F4 + (ki[r] * 3 + kj[cc]) * C4 + c4;
            float4 v = __ldg(&in[off]);
            acc.x += v.x; acc.y += v.y; acc.z += v.z; acc.w += v.w;
        }
    }
    out[idx] = acc;
}

extern "C" void kernel_launch(void* const* d_in, const int* in_sizes, int n_in,
                              void* d_out, int out_size) {
    (void)in_sizes; (void)n_in; (void)out_size;
    const float4* in = (const float4*)d_in[0];
    float4* out = (float4*)d_out;
    const int total = B * OUT * OUT * C4;          // 8388608
    fold_gather_kernel<<<total / 256, 256>>>(in, out);
}

// round 2
// speedup vs baseline: 1.2209x; 1.2209x over previous
#include <cuda_runtime.h>

// FoldLayer gather, 2x2-output-tile per thread.
// Input:  patches (16, 64, 64, 9*128) f32 kernel-major; Output: (16,128,128,128) f32.
// S=2, K=3, PAD=1: output pixel yo maps to canvas y=yo+1; contributors 2*gy+i==y.
// A 2x2 tile (yo=2ty,2ty+1)x(xo=2tx,2tx+1) reads exactly 9 input float4 from
// cells (ty,tx),(ty,tx+1),(ty+1,tx),(ty+1,tx+1) at fixed (i,j) offsets.

namespace {
constexpr int G   = 64;
constexpr int C4  = 32;                 // 128 channels / 4
constexpr int PATCH_F4 = 9 * C4;        // 288
}

__global__ __launch_bounds__(256) void fold_tile_kernel(
    const float4* __restrict__ in, float4* __restrict__ out)
{
    int idx = blockIdx.x * blockDim.x + threadIdx.x;
    int c4 = idx & (C4 - 1);
    int t  = idx >> 5;
    int tx = t & (G - 1);  t >>= 6;
    int ty = t & (G - 1);
    int b  = t >> 6;

    const bool vx = (tx + 1) < G;
    const bool vy = (ty + 1) < G;

    const float4* p = in + c4;
    int cell00 = ((b * G + ty) * G + tx) * PATCH_F4;
    int cell01 = cell00 + PATCH_F4;          // (ty, tx+1)
    int cell10 = cell00 + G * PATCH_F4;      // (ty+1, tx)
    int cell11 = cell10 + PATCH_F4;          // (ty+1, tx+1)

    const float4 z = make_float4(0.f, 0.f, 0.f, 0.f);
    // cell(ty,tx): (i,j) in {1,2}x{1,2}
    float4 a11 = __ldg(p + cell00 + 4 * C4);   // (1,1)
    float4 a12 = __ldg(p + cell00 + 5 * C4);   // (1,2)
    float4 a21 = __ldg(p + cell00 + 7 * C4);   // (2,1)
    float4 a22 = __ldg(p + cell00 + 8 * C4);   // (2,2)
    // cell(ty,tx+1): j=0, i in {1,2}
    float4 b10 = vx ? __ldg(p + cell01 + 3 * C4) : z;   // (1,0)
    float4 b20 = vx ? __ldg(p + cell01 + 6 * C4) : z;   // (2,0)
    // cell(ty+1,tx): i=0, j in {1,2}
    float4 c01 = vy ? __ldg(p + cell10 + 1 * C4) : z;   // (0,1)
    float4 c02 = vy ? __ldg(p + cell10 + 2 * C4) : z;   // (0,2)
    // cell(ty+1,tx+1): (0,0)
    float4 d00 = (vx && vy) ? __ldg(p + cell11) : z;

    float4 acc01, acc10, acc11;
    acc01.x = a12.x + b10.x; acc01.y = a12.y + b10.y;
    acc01.z = a12.z + b10.z; acc01.w = a12.w + b10.w;
    acc10.x = a21.x + c01.x; acc10.y = a21.y + c01.y;
    acc10.z = a21.z + c01.z; acc10.w = a21.w + c01.w;
    acc11.x = (a22.x + b20.x) + (c02.x + d00.x);
    acc11.y = (a22.y + b20.y) + (c02.y + d00.y);
    acc11.z = (a22.z + b20.z) + (c02.z + d00.z);
    acc11.w = (a22.w + b20.w) + (c02.w + d00.w);

    // out index: ((b*128 + yo)*128 + xo)*32 + c4, yo=2ty, xo=2tx
    int o00 = (((b << 7) + (ty << 1)) << 7) + (tx << 1);
    o00 = (o00 << 5) + c4;
    out[o00]              = a11;     // (yo, xo)
    out[o00 + C4]         = acc01;   // (yo, xo+1)
    out[o00 + 128 * C4]   = acc10;   // (yo+1, xo)
    out[o00 + 129 * C4]   = acc11;   // (yo+1, xo+1)
}

extern "C" void kernel_launch(void* const* d_in, const int* in_sizes, int n_in,
                              void* d_out, int out_size) {
    (void)in_sizes; (void)n_in; (void)out_size;
    const float4* in = (const float4*)d_in[0];
    float4* out = (float4*)d_out;
    const int total = 16 * G * G * C4;   // 2,097,152 threads
    fold_tile_kernel<<<total / 256, 256>>>(in, out);
}